// round 12
// baseline (speedup 1.0000x reference)
#include <cuda_runtime.h>
#include <cstdint>

// ===========================================================================
// JumpReLU SAE via mma.sync tf32. 2 CTAs/SM x 8 warps (16 warps/SM), warp
// tile 64x32, CTA tile 128x128. Per-CTA barriers let the co-resident CTA
// keep the tensor pipe busy during sync/epilogue (round-11 analysis: binder
// is tensor-pipe idle time, peak ~512 MAC/cyc/SM, not the smem crossbar).
//   prep:   W_encT = round_tf32(W_enc^T), W_decT = round_tf32(W_dec^T)
//           xR = round_tf32(x), bias_eff = b_enc - b_dec@W_enc (split-K)
//   GEMM1:  feats = round_tf32(JumpReLU(xR @ W_encT' + bias_eff)) -> d_out
//   GEMM2:  recon = feats @ W_decT' + b_dec
// ===========================================================================

#define BM 128
#define BN 128
#define BK 32
#define STAGES 3
#define NT 256            // 8 warps: 2 (M) x 4 (N), warp tile 64x32

#define ROWB 144                      // (BK+4)*4 B; 9x16B rows -> conflict-free ldmatrix
#define A_STAGE (BM * ROWB)           // 18432 B
#define B_STAGE (BN * ROWB)           // 18432 B
#define STAGE_BYTES (A_STAGE + B_STAGE)          // 36864 B
#define SMEM_TOTAL (STAGES * STAGE_BYTES)        // 110592 B (x2 CTAs = 221184)

#define BC_SPLIT 8        // split-K factor for bias correction

// ------------------------- device scratch (no allocs allowed) --------------
__device__ __align__(16) float g_WencT[(size_t)16384 * 2048];   // [n][k] tf32
__device__ __align__(16) float g_WdecT[(size_t)2048 * 16384];   // [n][k] tf32
__device__ __align__(16) float g_xR[(size_t)8192 * 2048];       // x tf32
__device__ __align__(16) float g_biasPart[BC_SPLIT * 16384];
__device__ __align__(16) float g_biasEnc[16384];

// ------------------------------ PTX helpers --------------------------------
__device__ __forceinline__ uint32_t smem_u32(const void* p) {
    uint32_t a;
    asm("{ .reg .u64 t; cvta.to.shared.u64 t, %1; cvt.u32.u64 %0, t; }"
        : "=r"(a) : "l"(p));
    return a;
}
__device__ __forceinline__ void cp_async16(uint32_t dst, const void* src) {
    asm volatile("cp.async.cg.shared.global [%0], [%1], 16;"
                 :: "r"(dst), "l"(src) : "memory");
}
__device__ __forceinline__ void cp_commit() {
    asm volatile("cp.async.commit_group;" ::: "memory");
}
template <int N>
__device__ __forceinline__ void cp_wait_group() {
    asm volatile("cp.async.wait_group %0;" :: "n"(N) : "memory");
}
__device__ __forceinline__ void ldmatrix_x4(uint32_t* r, uint32_t addr) {
    asm volatile("ldmatrix.sync.aligned.m8n8.x4.shared.b16 {%0, %1, %2, %3}, [%4];"
                 : "=r"(r[0]), "=r"(r[1]), "=r"(r[2]), "=r"(r[3]) : "r"(addr));
}
__device__ __forceinline__ float round_tf32(float v) {
    float d;
    asm("cvt.rna.tf32.f32 %0, %1;" : "=f"(d) : "f"(v));
    return d;
}
__device__ __forceinline__ void mma_tf32(float* c, const uint32_t* a,
                                         const uint32_t* b) {
    asm volatile(
        "mma.sync.aligned.m16n8k8.row.col.f32.tf32.tf32.f32 "
        "{%0, %1, %2, %3}, {%4, %5, %6, %7}, {%8, %9}, {%0, %1, %2, %3};"
        : "+f"(c[0]), "+f"(c[1]), "+f"(c[2]), "+f"(c[3])
        : "r"(a[0]), "r"(a[1]), "r"(a[2]), "r"(a[3]), "r"(b[0]), "r"(b[1]));
}

// ------------------------------- prep kernels ------------------------------
// dst[C][R] = round_tf32(src[R][C])
__global__ void transpose_round_kernel(const float* __restrict__ src,
                                       float* __restrict__ dst, int R, int C) {
    __shared__ float tile[32][33];
    int x = blockIdx.x * 32 + threadIdx.x;
    int y = blockIdx.y * 32 + threadIdx.y;
    #pragma unroll
    for (int j = 0; j < 32; j += 8)
        tile[threadIdx.y + j][threadIdx.x] =
            round_tf32(src[(size_t)(y + j) * C + x]);
    __syncthreads();
    x = blockIdx.y * 32 + threadIdx.x;
    y = blockIdx.x * 32 + threadIdx.y;
    #pragma unroll
    for (int j = 0; j < 32; j += 8)
        dst[(size_t)(y + j) * R + x] = tile[threadIdx.x][threadIdx.y + j];
}

__global__ void round_kernel(const float* __restrict__ src,
                             float* __restrict__ dst, size_t n4) {
    size_t i = (size_t)blockIdx.x * blockDim.x + threadIdx.x;
    if (i < n4) {
        float4 v = reinterpret_cast<const float4*>(src)[i];
        v.x = round_tf32(v.x); v.y = round_tf32(v.y);
        v.z = round_tf32(v.z); v.w = round_tf32(v.w);
        reinterpret_cast<float4*>(dst)[i] = v;
    }
}

// split-K partials: part[ky][n] = sum_{k in chunk ky} b_dec[k] * W_enc[k][n]
__global__ void bias_part_kernel(const float* __restrict__ W_enc,
                                 const float* __restrict__ b_dec,
                                 float* __restrict__ part, int K, int N) {
    const int n  = blockIdx.x * blockDim.x + threadIdx.x;
    const int ky = blockIdx.y;
    const int kc = K / BC_SPLIT;
    const int k0 = ky * kc;
    float s = 0.f;
    #pragma unroll 4
    for (int k = k0; k < k0 + kc; k++)
        s += b_dec[k] * W_enc[(size_t)k * N + n];
    part[(size_t)ky * N + n] = s;
}

// bias_eff[n] = b_enc[n] - sum_ky part[ky][n]   (deterministic reduce)
__global__ void bias_reduce_kernel(const float* __restrict__ part,
                                   const float* __restrict__ b_enc,
                                   float* __restrict__ out, int N) {
    const int n = blockIdx.x * blockDim.x + threadIdx.x;
    float s = 0.f;
    #pragma unroll
    for (int ky = 0; ky < BC_SPLIT; ky++)
        s += part[(size_t)ky * N + n];
    out[n] = b_enc[n] - s;
}

// ------------------------------- main GEMM ---------------------------------
// ENC: JumpReLU epilogue, output stored tf32-rounded (consumed by decode)
template <bool ENC>
__global__ __launch_bounds__(NT, 2)
void sae_gemm(const float* __restrict__ A,      // [M][K] K-contig, tf32 values
              const float* __restrict__ B,      // [Ntot][K] K-contig, tf32 values
              const float* __restrict__ bias,   // [Ntot]
              const float* __restrict__ thr,    // [Ntot] (ENC only)
              float* __restrict__ C,            // [M][Ntot]
              int K, int Nout) {
    extern __shared__ __align__(16) char smem[];
    const uint32_t sb = smem_u32(smem);

    const int tid = threadIdx.x;
    const int wid = tid >> 5;
    const int l   = tid & 31;
    const int wm  = wid & 1;        // 0..1 (M)
    const int wn  = wid >> 1;       // 0..3 (N)

    const float* Ag = A + (size_t)blockIdx.y * BM * K;
    const float* Bg = B + (size_t)blockIdx.x * BN * K;

    const int n_iters = K / BK;

    // cp.async mapping: 16B chunks, 256 threads, 4 chunks each for A and B.
    const int ldRow = tid >> 3;          // 0..31
    const int ldChk = tid & 7;           // 0..7
    const size_t ldSrc  = (size_t)ldRow * K + ldChk * 4;
    const uint32_t ldDst = (uint32_t)(ldRow * ROWB + ldChk * 16);

    auto issue_tile = [&](int t) {
        if (t < n_iters) {
            const uint32_t st = sb + (t % STAGES) * STAGE_BYTES;
            const int k0 = t * BK;
            const float* aS = Ag + k0;
            const float* bS = Bg + k0;
            #pragma unroll
            for (int i = 0; i < 4; i++)      // A: 128 rows
                cp_async16(st + ldDst + i * 32 * ROWB,
                           aS + ldSrc + (size_t)i * 32 * K);
            #pragma unroll
            for (int i = 0; i < 4; i++)      // B: 128 rows
                cp_async16(st + A_STAGE + ldDst + i * 32 * ROWB,
                           bS + ldSrc + (size_t)i * 32 * K);
        }
        cp_commit();   // uniform one group per slot (possibly empty)
    };

    // fragment smem byte-offsets (relative to stage base)
    uint32_t aoff[4], boff[2];
    #pragma unroll
    for (int i = 0; i < 4; i++)
        aoff[i] = (uint32_t)((wm * 64 + i * 16 + (l & 15)) * ROWB
                             + (l >> 4) * 16);
    #pragma unroll
    for (int j = 0; j < 2; j++)
        boff[j] = (uint32_t)(A_STAGE
                             + (wn * 32 + j * 16 + (l & 7) + ((l >> 4) << 3)) * ROWB
                             + ((l >> 3) & 1) * 16);

    float acc[4][4][4];
    #pragma unroll
    for (int i = 0; i < 4; i++)
        #pragma unroll
        for (int j = 0; j < 4; j++)
            #pragma unroll
            for (int q = 0; q < 4; q++) acc[i][j][q] = 0.f;

    issue_tile(0);
    issue_tile(1);

    for (int it = 0; it < n_iters; ++it) {
        cp_wait_group<1>();          // tile `it` resident
        __syncthreads();             // all warps done with iter it-1
        issue_tile(it + 2);          // writes slot (it-1)%3: safe after barrier

        const uint32_t st = sb + (it % STAGES) * STAGE_BYTES;
        #pragma unroll
        for (int ks = 0; ks < BK / 8; ks++) {
            uint32_t af[4][4], bf[2][4];
            #pragma unroll
            for (int i = 0; i < 4; i++)
                ldmatrix_x4(af[i], st + aoff[i] + ks * 32);
            #pragma unroll
            for (int j = 0; j < 2; j++)
                ldmatrix_x4(bf[j], st + boff[j] + ks * 32);
            #pragma unroll
            for (int i = 0; i < 4; i++) {
                mma_tf32(acc[i][0], af[i], &bf[0][0]);
                mma_tf32(acc[i][1], af[i], &bf[0][2]);
                mma_tf32(acc[i][2], af[i], &bf[1][0]);
                mma_tf32(acc[i][3], af[i], &bf[1][2]);
            }
        }
    }

    // ---- fused epilogue ----
    const int cRow = blockIdx.y * BM + wm * 64;
    const int cCol = blockIdx.x * BN + wn * 32;

    #pragma unroll
    for (int i = 0; i < 4; i++) {
        const int r0 = cRow + i * 16 + (l >> 2);
        #pragma unroll
        for (int j = 0; j < 4; j++) {
            const int col = cCol + j * 8 + (l & 3) * 2;
            const float2 bv = *reinterpret_cast<const float2*>(bias + col);
            float v0 = acc[i][j][0] + bv.x;
            float v1 = acc[i][j][1] + bv.y;
            float v2 = acc[i][j][2] + bv.x;
            float v3 = acc[i][j][3] + bv.y;
            if (ENC) {
                const float2 tv = *reinterpret_cast<const float2*>(thr + col);
                v0 = (v0 > tv.x) ? round_tf32(v0) : 0.f;
                v1 = (v1 > tv.y) ? round_tf32(v1) : 0.f;
                v2 = (v2 > tv.x) ? round_tf32(v2) : 0.f;
                v3 = (v3 > tv.y) ? round_tf32(v3) : 0.f;
            }
            const size_t o0 = (size_t)r0 * Nout + col;
            const size_t o1 = (size_t)(r0 + 8) * Nout + col;
            *reinterpret_cast<float2*>(C + o0) = make_float2(v0, v1);
            *reinterpret_cast<float2*>(C + o1) = make_float2(v2, v3);
        }
    }
}

// ------------------------------- launcher ----------------------------------
extern "C" void kernel_launch(void* const* d_in, const int* in_sizes, int n_in,
                              void* d_out, int out_size) {
    const float* x     = (const float*)d_in[0];   // [8192, 2048]
    const float* W_enc = (const float*)d_in[1];   // [2048, 16384]
    const float* b_enc = (const float*)d_in[2];   // [16384]
    const float* thr   = (const float*)d_in[3];   // [16384]
    const float* W_dec = (const float*)d_in[4];   // [16384, 2048]
    const float* b_dec = (const float*)d_in[5];   // [2048]

    const int Nrows = 8192, D = 2048, S = 16384;

    float* recon = (float*)d_out;                       // [8192, 2048]
    float* feats = (float*)d_out + (size_t)Nrows * D;   // [8192, 16384]

    float *wEncT, *wDecT, *xR, *biasPart, *biasEnc;
    cudaGetSymbolAddress((void**)&wEncT, g_WencT);
    cudaGetSymbolAddress((void**)&wDecT, g_WdecT);
    cudaGetSymbolAddress((void**)&xR, g_xR);
    cudaGetSymbolAddress((void**)&biasPart, g_biasPart);
    cudaGetSymbolAddress((void**)&biasEnc, g_biasEnc);

    cudaFuncSetAttribute(sae_gemm<true>,
                         cudaFuncAttributeMaxDynamicSharedMemorySize, SMEM_TOTAL);
    cudaFuncSetAttribute(sae_gemm<false>,
                         cudaFuncAttributeMaxDynamicSharedMemorySize, SMEM_TOTAL);

    // prep: tf32-rounded transposed weights, rounded x, effective encoder bias
    transpose_round_kernel<<<dim3(S / 32, D / 32), dim3(32, 8)>>>(W_enc, wEncT, D, S);
    transpose_round_kernel<<<dim3(D / 32, S / 32), dim3(32, 8)>>>(W_dec, wDecT, S, D);
    {
        size_t n4 = (size_t)Nrows * D / 4;
        round_kernel<<<(unsigned)((n4 + 255) / 256), 256>>>(x, xR, n4);
    }
    bias_part_kernel<<<dim3(S / 256, BC_SPLIT), 256>>>(W_enc, b_dec, biasPart, D, S);
    bias_reduce_kernel<<<S / 256, 256>>>(biasPart, b_enc, biasEnc, S);

    // encode: feats = round_tf32(JumpReLU(xR @ W_enc + bias_eff)) -> d_out
    sae_gemm<true><<<dim3(S / BN, Nrows / BM), NT, SMEM_TOTAL>>>(
        xR, wEncT, biasEnc, thr, feats, D, S);

    // decode: recon = feats @ W_dec + b_dec   (feats already tf32 values)
    sae_gemm<false><<<dim3(D / BN, Nrows / BM), NT, SMEM_TOTAL>>>(
        feats, wDecT, b_dec, nullptr, recon, S, D);
}

// round 13
// speedup vs baseline: 1.4260x; 1.4260x over previous
#include <cuda_runtime.h>
#include <cstdint>

// ===========================================================================
// JumpReLU SAE via mma.sync tf32. Round-10 skeleton (best: 6492us) plus:
//   (1) banded grid swizzle (8 M-tiles/band) -> weight matrix streamed from
//       DRAM once per band instead of once per M-tile row;
//   (2) 2-tile-per-barrier pipeline schedule (fewer wait drains, deeper MLP).
//   prep:   W_encT = round_tf32(W_enc^T), W_decT = round_tf32(W_dec^T)
//           xR = round_tf32(x), bias_eff = b_enc - b_dec@W_enc (split-K)
//   GEMM1:  feats = round_tf32(JumpReLU(xR @ W_encT' + bias_eff)) -> d_out
//   GEMM2:  recon = feats @ W_decT' + b_dec
// ===========================================================================

#define BM 128
#define BN 256
#define BK 32
#define STAGES 4
#define NT 512            // 16 warps: 2 (M) x 8 (N), warp tile 64x32

#define ROWB 144                      // (BK+4)*4 B; 9x16B rows -> conflict-free ldmatrix
#define A_STAGE (BM * ROWB)           // 18432 B
#define B_STAGE (BN * ROWB)           // 36864 B
#define STAGE_BYTES (A_STAGE + B_STAGE)          // 55296 B
#define SMEM_TOTAL (STAGES * STAGE_BYTES)        // 221184 B

#define BC_SPLIT 8        // split-K factor for bias correction
#define GY 8              // grid swizzle band height (M-tiles); gridy % GY == 0

// ------------------------- device scratch (no allocs allowed) --------------
__device__ __align__(16) float g_WencT[(size_t)16384 * 2048];   // [n][k] tf32
__device__ __align__(16) float g_WdecT[(size_t)2048 * 16384];   // [n][k] tf32
__device__ __align__(16) float g_xR[(size_t)8192 * 2048];       // x tf32
__device__ __align__(16) float g_biasPart[BC_SPLIT * 16384];
__device__ __align__(16) float g_biasEnc[16384];

// ------------------------------ PTX helpers --------------------------------
__device__ __forceinline__ uint32_t smem_u32(const void* p) {
    uint32_t a;
    asm("{ .reg .u64 t; cvta.to.shared.u64 t, %1; cvt.u32.u64 %0, t; }"
        : "=r"(a) : "l"(p));
    return a;
}
__device__ __forceinline__ void cp_async16(uint32_t dst, const void* src) {
    asm volatile("cp.async.cg.shared.global [%0], [%1], 16;"
                 :: "r"(dst), "l"(src) : "memory");
}
__device__ __forceinline__ void cp_commit() {
    asm volatile("cp.async.commit_group;" ::: "memory");
}
template <int N>
__device__ __forceinline__ void cp_wait_group() {
    asm volatile("cp.async.wait_group %0;" :: "n"(N) : "memory");
}
__device__ __forceinline__ void ldmatrix_x4(uint32_t* r, uint32_t addr) {
    asm volatile("ldmatrix.sync.aligned.m8n8.x4.shared.b16 {%0, %1, %2, %3}, [%4];"
                 : "=r"(r[0]), "=r"(r[1]), "=r"(r[2]), "=r"(r[3]) : "r"(addr));
}
__device__ __forceinline__ float round_tf32(float v) {
    float d;
    asm("cvt.rna.tf32.f32 %0, %1;" : "=f"(d) : "f"(v));
    return d;
}
__device__ __forceinline__ void mma_tf32(float* c, const uint32_t* a,
                                         const uint32_t* b) {
    asm volatile(
        "mma.sync.aligned.m16n8k8.row.col.f32.tf32.tf32.f32 "
        "{%0, %1, %2, %3}, {%4, %5, %6, %7}, {%8, %9}, {%0, %1, %2, %3};"
        : "+f"(c[0]), "+f"(c[1]), "+f"(c[2]), "+f"(c[3])
        : "r"(a[0]), "r"(a[1]), "r"(a[2]), "r"(a[3]), "r"(b[0]), "r"(b[1]));
}

// ------------------------------- prep kernels ------------------------------
// dst[C][R] = round_tf32(src[R][C])
__global__ void transpose_round_kernel(const float* __restrict__ src,
                                       float* __restrict__ dst, int R, int C) {
    __shared__ float tile[32][33];
    int x = blockIdx.x * 32 + threadIdx.x;
    int y = blockIdx.y * 32 + threadIdx.y;
    #pragma unroll
    for (int j = 0; j < 32; j += 8)
        tile[threadIdx.y + j][threadIdx.x] =
            round_tf32(src[(size_t)(y + j) * C + x]);
    __syncthreads();
    x = blockIdx.y * 32 + threadIdx.x;
    y = blockIdx.x * 32 + threadIdx.y;
    #pragma unroll
    for (int j = 0; j < 32; j += 8)
        dst[(size_t)(y + j) * R + x] = tile[threadIdx.x][threadIdx.y + j];
}

__global__ void round_kernel(const float* __restrict__ src,
                             float* __restrict__ dst, size_t n4) {
    size_t i = (size_t)blockIdx.x * blockDim.x + threadIdx.x;
    if (i < n4) {
        float4 v = reinterpret_cast<const float4*>(src)[i];
        v.x = round_tf32(v.x); v.y = round_tf32(v.y);
        v.z = round_tf32(v.z); v.w = round_tf32(v.w);
        reinterpret_cast<float4*>(dst)[i] = v;
    }
}

// split-K partials: part[ky][n] = sum_{k in chunk ky} b_dec[k] * W_enc[k][n]
__global__ void bias_part_kernel(const float* __restrict__ W_enc,
                                 const float* __restrict__ b_dec,
                                 float* __restrict__ part, int K, int N) {
    const int n  = blockIdx.x * blockDim.x + threadIdx.x;
    const int ky = blockIdx.y;
    const int kc = K / BC_SPLIT;
    const int k0 = ky * kc;
    float s = 0.f;
    #pragma unroll 4
    for (int k = k0; k < k0 + kc; k++)
        s += b_dec[k] * W_enc[(size_t)k * N + n];
    part[(size_t)ky * N + n] = s;
}

// bias_eff[n] = b_enc[n] - sum_ky part[ky][n]   (deterministic reduce)
__global__ void bias_reduce_kernel(const float* __restrict__ part,
                                   const float* __restrict__ b_enc,
                                   float* __restrict__ out, int N) {
    const int n = blockIdx.x * blockDim.x + threadIdx.x;
    float s = 0.f;
    #pragma unroll
    for (int ky = 0; ky < BC_SPLIT; ky++)
        s += part[(size_t)ky * N + n];
    out[n] = b_enc[n] - s;
}

// ------------------------------- main GEMM ---------------------------------
// ENC: JumpReLU epilogue, output stored tf32-rounded (consumed by decode)
template <bool ENC>
__global__ __launch_bounds__(NT, 1)
void sae_gemm(const float* __restrict__ A,      // [M][K] K-contig, tf32 values
              const float* __restrict__ B,      // [Ntot][K] K-contig, tf32 values
              const float* __restrict__ bias,   // [Ntot]
              const float* __restrict__ thr,    // [Ntot] (ENC only)
              float* __restrict__ C,            // [M][Ntot]
              int K, int Nout) {
    extern __shared__ __align__(16) char smem[];
    const uint32_t sb = smem_u32(smem);

    const int tid = threadIdx.x;
    const int wid = tid >> 5;
    const int l   = tid & 31;
    const int wm  = wid & 1;        // 0..1 (M)
    const int wn  = wid >> 1;       // 0..7 (N)

    // banded grid swizzle: consecutive CTAs share the same N-tile across a
    // band of GY M-tiles -> weight (B) tiles reused GY x within a wave, and
    // the full B matrix streams from DRAM once per band, not once per M-row.
    const int linear = blockIdx.y * gridDim.x + blockIdx.x;
    const int band   = linear / (GY * gridDim.x);
    const int rem    = linear - band * (GY * gridDim.x);
    const int by     = band * GY + (rem & (GY - 1));
    const int bx     = rem >> 3;            // rem / GY (GY == 8)

    const float* Ag = A + (size_t)by * BM * K;
    const float* Bg = B + (size_t)bx * BN * K;

    const int n_iters = K / BK;             // even for all our shapes

    // cp.async mapping: 16B chunks, 512 threads.
    const int ldRow = tid >> 3;          // 0..63
    const int ldChk = tid & 7;           // 0..7
    const size_t ldSrc  = (size_t)ldRow * K + ldChk * 4;
    const uint32_t ldDst = (uint32_t)(ldRow * ROWB + ldChk * 16);

    auto issue_tile = [&](int t) {
        if (t < n_iters) {
            const uint32_t st = sb + (t & (STAGES - 1)) * STAGE_BYTES;
            const int k0 = t * BK;
            const float* aS = Ag + k0;
            const float* bS = Bg + k0;
            #pragma unroll
            for (int i = 0; i < 2; i++)      // A: 128 rows
                cp_async16(st + ldDst + i * 64 * ROWB,
                           aS + ldSrc + (size_t)i * 64 * K);
            #pragma unroll
            for (int i = 0; i < 4; i++)      // B: 256 rows
                cp_async16(st + A_STAGE + ldDst + i * 64 * ROWB,
                           bS + ldSrc + (size_t)i * 64 * K);
        }
        cp_commit();   // uniform one group per slot (possibly empty)
    };

    // fragment smem byte-offsets (relative to stage base)
    uint32_t aoff[4], boff[2];
    #pragma unroll
    for (int i = 0; i < 4; i++)
        aoff[i] = (uint32_t)((wm * 64 + i * 16 + (l & 15)) * ROWB
                             + (l >> 4) * 16);
    #pragma unroll
    for (int j = 0; j < 2; j++)
        boff[j] = (uint32_t)(A_STAGE
                             + (wn * 32 + j * 16 + (l & 7) + ((l >> 4) << 3)) * ROWB
                             + ((l >> 3) & 1) * 16);

    float acc[4][4][4];
    #pragma unroll
    for (int i = 0; i < 4; i++)
        #pragma unroll
        for (int j = 0; j < 4; j++)
            #pragma unroll
            for (int q = 0; q < 4; q++) acc[i][j][q] = 0.f;

    auto compute_tile = [&](int t) {
        const uint32_t st = sb + (t & (STAGES - 1)) * STAGE_BYTES;
        #pragma unroll
        for (int ks = 0; ks < BK / 8; ks++) {
            uint32_t af[4][4], bf[2][4];
            #pragma unroll
            for (int i = 0; i < 4; i++)
                ldmatrix_x4(af[i], st + aoff[i] + ks * 32);
            #pragma unroll
            for (int j = 0; j < 2; j++)
                ldmatrix_x4(bf[j], st + boff[j] + ks * 32);
            #pragma unroll
            for (int i = 0; i < 4; i++) {
                mma_tf32(acc[i][0], af[i], &bf[0][0]);
                mma_tf32(acc[i][1], af[i], &bf[0][2]);
                mma_tf32(acc[i][2], af[i], &bf[1][0]);
                mma_tf32(acc[i][3], af[i], &bf[1][2]);
            }
        }
    };

    issue_tile(0);
    issue_tile(1);

    // 2 tiles per barrier pair. Safety: top sync certifies all warps finished
    // reading tiles it-2, it-1, whose slots (it+2)&3, (it+3)&3 we then refill;
    // wait_group<2> leaves only the 2 newest groups pending -> it, it+1 ready.
    for (int it = 0; it < n_iters; it += 2) {
        __syncthreads();
        issue_tile(it + 2);
        issue_tile(it + 3);
        cp_wait_group<2>();
        __syncthreads();
        compute_tile(it);
        compute_tile(it + 1);
    }

    // ---- fused epilogue ----
    const int cRow = by * BM + wm * 64;
    const int cCol = bx * BN + wn * 32;

    #pragma unroll
    for (int i = 0; i < 4; i++) {
        const int r0 = cRow + i * 16 + (l >> 2);
        #pragma unroll
        for (int j = 0; j < 4; j++) {
            const int col = cCol + j * 8 + (l & 3) * 2;
            const float2 bv = *reinterpret_cast<const float2*>(bias + col);
            float v0 = acc[i][j][0] + bv.x;
            float v1 = acc[i][j][1] + bv.y;
            float v2 = acc[i][j][2] + bv.x;
            float v3 = acc[i][j][3] + bv.y;
            if (ENC) {
                const float2 tv = *reinterpret_cast<const float2*>(thr + col);
                v0 = (v0 > tv.x) ? round_tf32(v0) : 0.f;
                v1 = (v1 > tv.y) ? round_tf32(v1) : 0.f;
                v2 = (v2 > tv.x) ? round_tf32(v2) : 0.f;
                v3 = (v3 > tv.y) ? round_tf32(v3) : 0.f;
            }
            const size_t o0 = (size_t)r0 * Nout + col;
            const size_t o1 = (size_t)(r0 + 8) * Nout + col;
            *reinterpret_cast<float2*>(C + o0) = make_float2(v0, v1);
            *reinterpret_cast<float2*>(C + o1) = make_float2(v2, v3);
        }
    }
}

// ------------------------------- launcher ----------------------------------
extern "C" void kernel_launch(void* const* d_in, const int* in_sizes, int n_in,
                              void* d_out, int out_size) {
    const float* x     = (const float*)d_in[0];   // [8192, 2048]
    const float* W_enc = (const float*)d_in[1];   // [2048, 16384]
    const float* b_enc = (const float*)d_in[2];   // [16384]
    const float* thr   = (const float*)d_in[3];   // [16384]
    const float* W_dec = (const float*)d_in[4];   // [16384, 2048]
    const float* b_dec = (const float*)d_in[5];   // [2048]

    const int Nrows = 8192, D = 2048, S = 16384;

    float* recon = (float*)d_out;                       // [8192, 2048]
    float* feats = (float*)d_out + (size_t)Nrows * D;   // [8192, 16384]

    float *wEncT, *wDecT, *xR, *biasPart, *biasEnc;
    cudaGetSymbolAddress((void**)&wEncT, g_WencT);
    cudaGetSymbolAddress((void**)&wDecT, g_WdecT);
    cudaGetSymbolAddress((void**)&xR, g_xR);
    cudaGetSymbolAddress((void**)&biasPart, g_biasPart);
    cudaGetSymbolAddress((void**)&biasEnc, g_biasEnc);

    cudaFuncSetAttribute(sae_gemm<true>,
                         cudaFuncAttributeMaxDynamicSharedMemorySize, SMEM_TOTAL);
    cudaFuncSetAttribute(sae_gemm<false>,
                         cudaFuncAttributeMaxDynamicSharedMemorySize, SMEM_TOTAL);

    // prep: tf32-rounded transposed weights, rounded x, effective encoder bias
    transpose_round_kernel<<<dim3(S / 32, D / 32), dim3(32, 8)>>>(W_enc, wEncT, D, S);
    transpose_round_kernel<<<dim3(D / 32, S / 32), dim3(32, 8)>>>(W_dec, wDecT, S, D);
    {
        size_t n4 = (size_t)Nrows * D / 4;
        round_kernel<<<(unsigned)((n4 + 255) / 256), 256>>>(x, xR, n4);
    }
    bias_part_kernel<<<dim3(S / 256, BC_SPLIT), 256>>>(W_enc, b_dec, biasPart, D, S);
    bias_reduce_kernel<<<S / 256, 256>>>(biasPart, b_enc, biasEnc, S);

    // encode: feats = round_tf32(JumpReLU(xR @ W_enc + bias_eff)) -> d_out
    sae_gemm<true><<<dim3(S / BN, Nrows / BM), NT, SMEM_TOTAL>>>(
        xR, wEncT, biasEnc, thr, feats, D, S);

    // decode: recon = feats @ W_dec + b_dec   (feats already tf32 values)
    sae_gemm<false><<<dim3(D / BN, Nrows / BM), NT, SMEM_TOTAL>>>(
        feats, wDecT, b_dec, nullptr, recon, S, D);
}

// round 14
// speedup vs baseline: 1.5298x; 1.0728x over previous
#include <cuda_runtime.h>
#include <cstdint>

// ===========================================================================
// JumpReLU SAE via mma.sync tf32 (round-10 mainloop: HMMA issue floor).
//   prep:   W_encT = round_tf32(W_enc^T), W_decT = round_tf32(W_dec^T)
//           xR = round_tf32(x), bias_eff = b_enc - b_dec@W_enc (split-K)
//   GEMM1:  feats = round_tf32(JumpReLU(xR @ W_encT' + bias_eff)) -> d_out
//   GEMM2:  decode split-K=2 (wave quantization: 512 tiles/148 SMs = 3.46
//           waves -> 4; split gives 1024 CTAs = 6.92 -> 7, tail 13.5% -> 1%)
//           partials -> scratch, combine: recon = p0 + p1 + b_dec
// ===========================================================================

#define BM 128
#define BN 256
#define BK 32
#define STAGES 4
#define NT 512            // 16 warps: 2 (M) x 8 (N), warp tile 64x32

#define ROWB 144                      // (BK+4)*4 B; 9x16B rows -> conflict-free ldmatrix
#define A_STAGE (BM * ROWB)           // 18432 B
#define B_STAGE (BN * ROWB)           // 36864 B
#define STAGE_BYTES (A_STAGE + B_STAGE)          // 55296 B
#define SMEM_TOTAL (STAGES * STAGE_BYTES)        // 221184 B

#define BC_SPLIT 8        // split-K factor for bias correction
#define DEC_SPLIT 2       // decode split-K factor (wave quantization fix)

// ------------------------- device scratch (no allocs allowed) --------------
__device__ __align__(16) float g_WencT[(size_t)16384 * 2048];   // [n][k] tf32
__device__ __align__(16) float g_WdecT[(size_t)2048 * 16384];   // [n][k] tf32
__device__ __align__(16) float g_xR[(size_t)8192 * 2048];       // x tf32
__device__ __align__(16) float g_decPart[(size_t)DEC_SPLIT * 8192 * 2048];
__device__ __align__(16) float g_biasPart[BC_SPLIT * 16384];
__device__ __align__(16) float g_biasEnc[16384];

// ------------------------------ PTX helpers --------------------------------
__device__ __forceinline__ uint32_t smem_u32(const void* p) {
    uint32_t a;
    asm("{ .reg .u64 t; cvta.to.shared.u64 t, %1; cvt.u32.u64 %0, t; }"
        : "=r"(a) : "l"(p));
    return a;
}
__device__ __forceinline__ void cp_async16(uint32_t dst, const void* src) {
    asm volatile("cp.async.cg.shared.global [%0], [%1], 16;"
                 :: "r"(dst), "l"(src) : "memory");
}
__device__ __forceinline__ void cp_commit() {
    asm volatile("cp.async.commit_group;" ::: "memory");
}
template <int N>
__device__ __forceinline__ void cp_wait_group() {
    asm volatile("cp.async.wait_group %0;" :: "n"(N) : "memory");
}
__device__ __forceinline__ void ldmatrix_x4(uint32_t* r, uint32_t addr) {
    asm volatile("ldmatrix.sync.aligned.m8n8.x4.shared.b16 {%0, %1, %2, %3}, [%4];"
                 : "=r"(r[0]), "=r"(r[1]), "=r"(r[2]), "=r"(r[3]) : "r"(addr));
}
__device__ __forceinline__ float round_tf32(float v) {
    float d;
    asm("cvt.rna.tf32.f32 %0, %1;" : "=f"(d) : "f"(v));
    return d;
}
__device__ __forceinline__ void mma_tf32(float* c, const uint32_t* a,
                                         const uint32_t* b) {
    asm volatile(
        "mma.sync.aligned.m16n8k8.row.col.f32.tf32.tf32.f32 "
        "{%0, %1, %2, %3}, {%4, %5, %6, %7}, {%8, %9}, {%0, %1, %2, %3};"
        : "+f"(c[0]), "+f"(c[1]), "+f"(c[2]), "+f"(c[3])
        : "r"(a[0]), "r"(a[1]), "r"(a[2]), "r"(a[3]), "r"(b[0]), "r"(b[1]));
}

// ------------------------------- prep kernels ------------------------------
// dst[C][R] = round_tf32(src[R][C])
__global__ void transpose_round_kernel(const float* __restrict__ src,
                                       float* __restrict__ dst, int R, int C) {
    __shared__ float tile[32][33];
    int x = blockIdx.x * 32 + threadIdx.x;
    int y = blockIdx.y * 32 + threadIdx.y;
    #pragma unroll
    for (int j = 0; j < 32; j += 8)
        tile[threadIdx.y + j][threadIdx.x] =
            round_tf32(src[(size_t)(y + j) * C + x]);
    __syncthreads();
    x = blockIdx.y * 32 + threadIdx.x;
    y = blockIdx.x * 32 + threadIdx.y;
    #pragma unroll
    for (int j = 0; j < 32; j += 8)
        dst[(size_t)(y + j) * R + x] = tile[threadIdx.x][threadIdx.y + j];
}

__global__ void round_kernel(const float* __restrict__ src,
                             float* __restrict__ dst, size_t n4) {
    size_t i = (size_t)blockIdx.x * blockDim.x + threadIdx.x;
    if (i < n4) {
        float4 v = reinterpret_cast<const float4*>(src)[i];
        v.x = round_tf32(v.x); v.y = round_tf32(v.y);
        v.z = round_tf32(v.z); v.w = round_tf32(v.w);
        reinterpret_cast<float4*>(dst)[i] = v;
    }
}

// split-K partials: part[ky][n] = sum_{k in chunk ky} b_dec[k] * W_enc[k][n]
__global__ void bias_part_kernel(const float* __restrict__ W_enc,
                                 const float* __restrict__ b_dec,
                                 float* __restrict__ part, int K, int N) {
    const int n  = blockIdx.x * blockDim.x + threadIdx.x;
    const int ky = blockIdx.y;
    const int kc = K / BC_SPLIT;
    const int k0 = ky * kc;
    float s = 0.f;
    #pragma unroll 4
    for (int k = k0; k < k0 + kc; k++)
        s += b_dec[k] * W_enc[(size_t)k * N + n];
    part[(size_t)ky * N + n] = s;
}

// bias_eff[n] = b_enc[n] - sum_ky part[ky][n]   (deterministic reduce)
__global__ void bias_reduce_kernel(const float* __restrict__ part,
                                   const float* __restrict__ b_enc,
                                   float* __restrict__ out, int N) {
    const int n = blockIdx.x * blockDim.x + threadIdx.x;
    float s = 0.f;
    #pragma unroll
    for (int ky = 0; ky < BC_SPLIT; ky++)
        s += part[(size_t)ky * N + n];
    out[n] = b_enc[n] - s;
}

// recon[i] = p0[i] + p1[i] + b_dec[i % D]  (deterministic combine)
__global__ void dec_combine_kernel(const float* __restrict__ part,
                                   const float* __restrict__ b_dec,
                                   float* __restrict__ out,
                                   int D, size_t n4) {
    size_t i = (size_t)blockIdx.x * blockDim.x + threadIdx.x;
    if (i < n4) {
        const size_t half = n4;   // elements4 per partial
        float4 a = reinterpret_cast<const float4*>(part)[i];
        float4 b = reinterpret_cast<const float4*>(part)[i + half];
        const int col = (int)((i * 4) & (size_t)(D - 1));
        const float4 bd = *reinterpret_cast<const float4*>(b_dec + col);
        float4 o;
        o.x = a.x + b.x + bd.x;
        o.y = a.y + b.y + bd.y;
        o.z = a.z + b.z + bd.z;
        o.w = a.w + b.w + bd.w;
        reinterpret_cast<float4*>(out)[i] = o;
    }
}

// ------------------------------- main GEMM ---------------------------------
// MODE 0: encode  — JumpReLU epilogue, output tf32-rounded, full K
// MODE 1: decode partial — K split by blockIdx.z, raw accumulator out (no bias)
template <int MODE>
__global__ __launch_bounds__(NT, 1)
void sae_gemm(const float* __restrict__ A,      // [M][K] K-contig, tf32 values
              const float* __restrict__ B,      // [Ntot][K] K-contig, tf32 values
              const float* __restrict__ bias,   // [Ntot] (MODE 0)
              const float* __restrict__ thr,    // [Ntot] (MODE 0)
              float* __restrict__ C,            // [M][Ntot] (or partials)
              int K, int Nout) {
    extern __shared__ __align__(16) char smem[];
    const uint32_t sb = smem_u32(smem);

    const int tid = threadIdx.x;
    const int wid = tid >> 5;
    const int l   = tid & 31;
    const int wm  = wid & 1;        // 0..1 (M)
    const int wn  = wid >> 1;       // 0..7 (N)

    // K range for this CTA (decode: half-K per blockIdx.z)
    const int Kc    = (MODE == 1) ? (K / DEC_SPLIT) : K;
    const int kbase = (MODE == 1) ? (blockIdx.z * Kc) : 0;

    const float* Ag = A + (size_t)blockIdx.y * BM * K + kbase;
    const float* Bg = B + (size_t)blockIdx.x * BN * K + kbase;

    const int n_iters = Kc / BK;

    // cp.async mapping: 16B chunks, 512 threads.
    const int ldRow = tid >> 3;          // 0..63
    const int ldChk = tid & 7;           // 0..7
    const size_t ldSrc  = (size_t)ldRow * K + ldChk * 4;
    const uint32_t ldDst = (uint32_t)(ldRow * ROWB + ldChk * 16);

    auto issue_tile = [&](int t) {
        if (t < n_iters) {
            const uint32_t st = sb + (t & (STAGES - 1)) * STAGE_BYTES;
            const int k0 = t * BK;
            const float* aS = Ag + k0;
            const float* bS = Bg + k0;
            #pragma unroll
            for (int i = 0; i < 2; i++)      // A: 128 rows
                cp_async16(st + ldDst + i * 64 * ROWB,
                           aS + ldSrc + (size_t)i * 64 * K);
            #pragma unroll
            for (int i = 0; i < 4; i++)      // B: 256 rows
                cp_async16(st + A_STAGE + ldDst + i * 64 * ROWB,
                           bS + ldSrc + (size_t)i * 64 * K);
        }
        cp_commit();   // uniform one group per slot (possibly empty)
    };

    // fragment smem byte-offsets (relative to stage base)
    uint32_t aoff[4], boff[2];
    #pragma unroll
    for (int i = 0; i < 4; i++)
        aoff[i] = (uint32_t)((wm * 64 + i * 16 + (l & 15)) * ROWB
                             + (l >> 4) * 16);
    #pragma unroll
    for (int j = 0; j < 2; j++)
        boff[j] = (uint32_t)(A_STAGE
                             + (wn * 32 + j * 16 + (l & 7) + ((l >> 4) << 3)) * ROWB
                             + ((l >> 3) & 1) * 16);

    float acc[4][4][4];
    #pragma unroll
    for (int i = 0; i < 4; i++)
        #pragma unroll
        for (int j = 0; j < 4; j++)
            #pragma unroll
            for (int q = 0; q < 4; q++) acc[i][j][q] = 0.f;

    issue_tile(0);
    issue_tile(1);
    issue_tile(2);

    for (int it = 0; it < n_iters; ++it) {
        cp_wait_group<2>();          // tile `it` resident
        __syncthreads();             // all warps done with iter it-1
        issue_tile(it + 3);          // writes slot (it-1)%4: safe after barrier

        const uint32_t st = sb + (it & (STAGES - 1)) * STAGE_BYTES;
        #pragma unroll
        for (int ks = 0; ks < BK / 8; ks++) {
            uint32_t af[4][4], bf[2][4];
            #pragma unroll
            for (int i = 0; i < 4; i++)
                ldmatrix_x4(af[i], st + aoff[i] + ks * 32);
            #pragma unroll
            for (int j = 0; j < 2; j++)
                ldmatrix_x4(bf[j], st + boff[j] + ks * 32);
            #pragma unroll
            for (int i = 0; i < 4; i++) {
                mma_tf32(acc[i][0], af[i], &bf[0][0]);
                mma_tf32(acc[i][1], af[i], &bf[0][2]);
                mma_tf32(acc[i][2], af[i], &bf[1][0]);
                mma_tf32(acc[i][3], af[i], &bf[1][2]);
            }
        }
    }

    // ---- fused epilogue ----
    const int cRow = blockIdx.y * BM + wm * 64;
    const int cCol = blockIdx.x * BN + wn * 32;
    // decode partial: offset into the per-split partial buffer
    float* Cb = (MODE == 1)
        ? C + (size_t)blockIdx.z * 8192 * 2048
        : C;

    #pragma unroll
    for (int i = 0; i < 4; i++) {
        const int r0 = cRow + i * 16 + (l >> 2);
        #pragma unroll
        for (int j = 0; j < 4; j++) {
            const int col = cCol + j * 8 + (l & 3) * 2;
            float v0 = acc[i][j][0];
            float v1 = acc[i][j][1];
            float v2 = acc[i][j][2];
            float v3 = acc[i][j][3];
            if (MODE == 0) {
                const float2 bv = *reinterpret_cast<const float2*>(bias + col);
                const float2 tv = *reinterpret_cast<const float2*>(thr + col);
                v0 += bv.x; v1 += bv.y; v2 += bv.x; v3 += bv.y;
                v0 = (v0 > tv.x) ? round_tf32(v0) : 0.f;
                v1 = (v1 > tv.y) ? round_tf32(v1) : 0.f;
                v2 = (v2 > tv.x) ? round_tf32(v2) : 0.f;
                v3 = (v3 > tv.y) ? round_tf32(v3) : 0.f;
            }
            const size_t o0 = (size_t)r0 * Nout + col;
            const size_t o1 = (size_t)(r0 + 8) * Nout + col;
            *reinterpret_cast<float2*>(Cb + o0) = make_float2(v0, v1);
            *reinterpret_cast<float2*>(Cb + o1) = make_float2(v2, v3);
        }
    }
}

// ------------------------------- launcher ----------------------------------
extern "C" void kernel_launch(void* const* d_in, const int* in_sizes, int n_in,
                              void* d_out, int out_size) {
    const float* x     = (const float*)d_in[0];   // [8192, 2048]
    const float* W_enc = (const float*)d_in[1];   // [2048, 16384]
    const float* b_enc = (const float*)d_in[2];   // [16384]
    const float* thr   = (const float*)d_in[3];   // [16384]
    const float* W_dec = (const float*)d_in[4];   // [16384, 2048]
    const float* b_dec = (const float*)d_in[5];   // [2048]

    const int Nrows = 8192, D = 2048, S = 16384;

    float* recon = (float*)d_out;                       // [8192, 2048]
    float* feats = (float*)d_out + (size_t)Nrows * D;   // [8192, 16384]

    float *wEncT, *wDecT, *xR, *decPart, *biasPart, *biasEnc;
    cudaGetSymbolAddress((void**)&wEncT, g_WencT);
    cudaGetSymbolAddress((void**)&wDecT, g_WdecT);
    cudaGetSymbolAddress((void**)&xR, g_xR);
    cudaGetSymbolAddress((void**)&decPart, g_decPart);
    cudaGetSymbolAddress((void**)&biasPart, g_biasPart);
    cudaGetSymbolAddress((void**)&biasEnc, g_biasEnc);

    cudaFuncSetAttribute(sae_gemm<0>,
                         cudaFuncAttributeMaxDynamicSharedMemorySize, SMEM_TOTAL);
    cudaFuncSetAttribute(sae_gemm<1>,
                         cudaFuncAttributeMaxDynamicSharedMemorySize, SMEM_TOTAL);

    // prep: tf32-rounded transposed weights, rounded x, effective encoder bias
    transpose_round_kernel<<<dim3(S / 32, D / 32), dim3(32, 8)>>>(W_enc, wEncT, D, S);
    transpose_round_kernel<<<dim3(D / 32, S / 32), dim3(32, 8)>>>(W_dec, wDecT, S, D);
    {
        size_t n4 = (size_t)Nrows * D / 4;
        round_kernel<<<(unsigned)((n4 + 255) / 256), 256>>>(x, xR, n4);
    }
    bias_part_kernel<<<dim3(S / 256, BC_SPLIT), 256>>>(W_enc, b_dec, biasPart, D, S);
    bias_reduce_kernel<<<S / 256, 256>>>(biasPart, b_enc, biasEnc, S);

    // encode: feats = round_tf32(JumpReLU(xR @ W_enc + bias_eff)) -> d_out
    sae_gemm<0><<<dim3(S / BN, Nrows / BM), NT, SMEM_TOTAL>>>(
        xR, wEncT, biasEnc, thr, feats, D, S);

    // decode split-K: 1024 CTAs (6.92 waves vs 3.46) -> partials
    sae_gemm<1><<<dim3(D / BN, Nrows / BM, DEC_SPLIT), NT, SMEM_TOTAL>>>(
        feats, wDecT, nullptr, nullptr, decPart, S, D);

    // combine: recon = p0 + p1 + b_dec
    {
        size_t n4 = (size_t)Nrows * D / 4;
        dec_combine_kernel<<<(unsigned)((n4 + 255) / 256), 256>>>(
            decPart, b_dec, recon, D, n4);
    }
}

// round 15
// speedup vs baseline: 1.5370x; 1.0047x over previous
#include <cuda_runtime.h>
#include <cstdint>

// ===========================================================================
// JumpReLU SAE via mma.sync tf32 (round-14 best: 6104us) + fused prep.
//   fused_prep (ONE launch, tasks by blockIdx range -> co-resident on SMs):
//     [0,1024)      bias partials (split-K=16): b_dec @ W_enc chunks
//     [..+32768)    W_encT = round_tf32(W_enc^T)
//     [..+16384)    xR = round_tf32(x)
//     [..+32768)    W_decT = round_tf32(W_dec^T)
//   bias_reduce: bias_eff = b_enc - sum(partials)
//   GEMM1: feats = round_tf32(JumpReLU(xR @ W_encT' + bias_eff)) -> d_out
//   GEMM2: decode split-K=2 -> partials; combine: recon = p0 + p1 + b_dec
// ===========================================================================

#define BM 128
#define BN 256
#define BK 32
#define STAGES 4
#define NT 512            // 16 warps: 2 (M) x 8 (N), warp tile 64x32

#define ROWB 144                      // (BK+4)*4 B; 9x16B rows -> conflict-free ldmatrix
#define A_STAGE (BM * ROWB)           // 18432 B
#define B_STAGE (BN * ROWB)           // 36864 B
#define STAGE_BYTES (A_STAGE + B_STAGE)          // 55296 B
#define SMEM_TOTAL (STAGES * STAGE_BYTES)        // 221184 B

#define BC_SPLIT 16       // split-K factor for bias correction
#define DEC_SPLIT 2       // decode split-K factor (wave quantization fix)

// fused-prep grid layout (block = 256 threads)
#define NB_BIAS (64 * BC_SPLIT)            // 1024   (16384/256 n-blocks x 16)
#define NB_TE   (512 * 64)                 // 32768  W_enc^T: C/32=512, R/32=64
#define NB_RD   16384                      // x round: 8192*2048/4/256
#define NB_TD   (64 * 512)                 // 32768  W_dec^T: C/32=64, R/32=512
#define NB_ALL  (NB_BIAS + NB_TE + NB_RD + NB_TD)

// ------------------------- device scratch (no allocs allowed) --------------
__device__ __align__(16) float g_WencT[(size_t)16384 * 2048];   // [n][k] tf32
__device__ __align__(16) float g_WdecT[(size_t)2048 * 16384];   // [n][k] tf32
__device__ __align__(16) float g_xR[(size_t)8192 * 2048];       // x tf32
__device__ __align__(16) float g_decPart[(size_t)DEC_SPLIT * 8192 * 2048];
__device__ __align__(16) float g_biasPart[BC_SPLIT * 16384];
__device__ __align__(16) float g_biasEnc[16384];

// ------------------------------ PTX helpers --------------------------------
__device__ __forceinline__ uint32_t smem_u32(const void* p) {
    uint32_t a;
    asm("{ .reg .u64 t; cvta.to.shared.u64 t, %1; cvt.u32.u64 %0, t; }"
        : "=r"(a) : "l"(p));
    return a;
}
__device__ __forceinline__ void cp_async16(uint32_t dst, const void* src) {
    asm volatile("cp.async.cg.shared.global [%0], [%1], 16;"
                 :: "r"(dst), "l"(src) : "memory");
}
__device__ __forceinline__ void cp_commit() {
    asm volatile("cp.async.commit_group;" ::: "memory");
}
template <int N>
__device__ __forceinline__ void cp_wait_group() {
    asm volatile("cp.async.wait_group %0;" :: "n"(N) : "memory");
}
__device__ __forceinline__ void ldmatrix_x4(uint32_t* r, uint32_t addr) {
    asm volatile("ldmatrix.sync.aligned.m8n8.x4.shared.b16 {%0, %1, %2, %3}, [%4];"
                 : "=r"(r[0]), "=r"(r[1]), "=r"(r[2]), "=r"(r[3]) : "r"(addr));
}
__device__ __forceinline__ float round_tf32(float v) {
    float d;
    asm("cvt.rna.tf32.f32 %0, %1;" : "=f"(d) : "f"(v));
    return d;
}
__device__ __forceinline__ void mma_tf32(float* c, const uint32_t* a,
                                         const uint32_t* b) {
    asm volatile(
        "mma.sync.aligned.m16n8k8.row.col.f32.tf32.tf32.f32 "
        "{%0, %1, %2, %3}, {%4, %5, %6, %7}, {%8, %9}, {%0, %1, %2, %3};"
        : "+f"(c[0]), "+f"(c[1]), "+f"(c[2]), "+f"(c[3])
        : "r"(a[0]), "r"(a[1]), "r"(a[2]), "r"(a[3]), "r"(b[0]), "r"(b[1]));
}

// ------------------------------- fused prep --------------------------------
// One launch; independent tasks share the chip and saturate DRAM together.
__device__ __forceinline__ void transpose_body(const float* __restrict__ src,
                                               float* __restrict__ dst,
                                               int R, int C, int blk, int tid,
                                               float (*tile)[33]) {
    const int gx = C / 32;
    const int bx = blk % gx;
    const int by = blk / gx;
    const int tx = tid & 31;
    const int ty = tid >> 5;          // 0..7
    int x = bx * 32 + tx;
    int y = by * 32 + ty;
    #pragma unroll
    for (int j = 0; j < 32; j += 8)
        tile[ty + j][tx] = round_tf32(src[(size_t)(y + j) * C + x]);
    __syncthreads();
    x = by * 32 + tx;
    y = bx * 32 + ty;
    #pragma unroll
    for (int j = 0; j < 32; j += 8)
        dst[(size_t)(y + j) * R + x] = tile[tx][ty + j];
}

__global__ __launch_bounds__(256)
void fused_prep(const float* __restrict__ W_enc,   // [2048][16384]
                const float* __restrict__ W_dec,   // [16384][2048]
                const float* __restrict__ x,       // [8192][2048]
                const float* __restrict__ b_dec,   // [2048]
                float* __restrict__ wEncT,
                float* __restrict__ wDecT,
                float* __restrict__ xR,
                float* __restrict__ biasPart) {
    __shared__ float tile[32][33];
    const int tid = threadIdx.x;
    int b = blockIdx.x;

    if (b < NB_BIAS) {
        // bias partials: part[ky][n] = sum_{k in chunk ky} b_dec[k]*W_enc[k][n]
        const int bx = b & 63;            // 64 n-blocks
        const int ky = b >> 6;            // 0..15
        const int n  = bx * 256 + tid;
        const int kc = 2048 / BC_SPLIT;   // 128
        const int k0 = ky * kc;
        float s = 0.f;
        #pragma unroll 4
        for (int k = k0; k < k0 + kc; k++)
            s += b_dec[k] * W_enc[(size_t)k * 16384 + n];
        biasPart[(size_t)ky * 16384 + n] = s;
        return;
    }
    b -= NB_BIAS;
    if (b < NB_TE) {   // W_encT = round(W_enc^T), R=2048, C=16384
        transpose_body(W_enc, wEncT, 2048, 16384, b, tid, tile);
        return;
    }
    b -= NB_TE;
    if (b < NB_RD) {   // xR = round(x)
        const size_t i = (size_t)b * 256 + tid;
        float4 v = reinterpret_cast<const float4*>(x)[i];
        v.x = round_tf32(v.x); v.y = round_tf32(v.y);
        v.z = round_tf32(v.z); v.w = round_tf32(v.w);
        reinterpret_cast<float4*>(xR)[i] = v;
        return;
    }
    b -= NB_RD;
    // W_decT = round(W_dec^T), R=16384, C=2048
    transpose_body(W_dec, wDecT, 16384, 2048, b, tid, tile);
}

// bias_eff[n] = b_enc[n] - sum_ky part[ky][n]   (deterministic reduce)
__global__ void bias_reduce_kernel(const float* __restrict__ part,
                                   const float* __restrict__ b_enc,
                                   float* __restrict__ out, int N) {
    const int n = blockIdx.x * blockDim.x + threadIdx.x;
    float s = 0.f;
    #pragma unroll
    for (int ky = 0; ky < BC_SPLIT; ky++)
        s += part[(size_t)ky * N + n];
    out[n] = b_enc[n] - s;
}

// recon[i] = p0[i] + p1[i] + b_dec[i % D]  (deterministic combine)
__global__ void dec_combine_kernel(const float* __restrict__ part,
                                   const float* __restrict__ b_dec,
                                   float* __restrict__ out,
                                   int D, size_t n4) {
    size_t i = (size_t)blockIdx.x * blockDim.x + threadIdx.x;
    if (i < n4) {
        const size_t half = n4;   // elements4 per partial
        float4 a = reinterpret_cast<const float4*>(part)[i];
        float4 b = reinterpret_cast<const float4*>(part)[i + half];
        const int col = (int)((i * 4) & (size_t)(D - 1));
        const float4 bd = *reinterpret_cast<const float4*>(b_dec + col);
        float4 o;
        o.x = a.x + b.x + bd.x;
        o.y = a.y + b.y + bd.y;
        o.z = a.z + b.z + bd.z;
        o.w = a.w + b.w + bd.w;
        reinterpret_cast<float4*>(out)[i] = o;
    }
}

// ------------------------------- main GEMM ---------------------------------
// MODE 0: encode  — JumpReLU epilogue, output tf32-rounded, full K
// MODE 1: decode partial — K split by blockIdx.z, raw accumulator out (no bias)
template <int MODE>
__global__ __launch_bounds__(NT, 1)
void sae_gemm(const float* __restrict__ A,      // [M][K] K-contig, tf32 values
              const float* __restrict__ B,      // [Ntot][K] K-contig, tf32 values
              const float* __restrict__ bias,   // [Ntot] (MODE 0)
              const float* __restrict__ thr,    // [Ntot] (MODE 0)
              float* __restrict__ C,            // [M][Ntot] (or partials)
              int K, int Nout) {
    extern __shared__ __align__(16) char smem[];
    const uint32_t sb = smem_u32(smem);

    const int tid = threadIdx.x;
    const int wid = tid >> 5;
    const int l   = tid & 31;
    const int wm  = wid & 1;        // 0..1 (M)
    const int wn  = wid >> 1;       // 0..7 (N)

    // K range for this CTA (decode: half-K per blockIdx.z)
    const int Kc    = (MODE == 1) ? (K / DEC_SPLIT) : K;
    const int kbase = (MODE == 1) ? (blockIdx.z * Kc) : 0;

    const float* Ag = A + (size_t)blockIdx.y * BM * K + kbase;
    const float* Bg = B + (size_t)blockIdx.x * BN * K + kbase;

    const int n_iters = Kc / BK;

    // cp.async mapping: 16B chunks, 512 threads.
    const int ldRow = tid >> 3;          // 0..63
    const int ldChk = tid & 7;           // 0..7
    const size_t ldSrc  = (size_t)ldRow * K + ldChk * 4;
    const uint32_t ldDst = (uint32_t)(ldRow * ROWB + ldChk * 16);

    auto issue_tile = [&](int t) {
        if (t < n_iters) {
            const uint32_t st = sb + (t & (STAGES - 1)) * STAGE_BYTES;
            const int k0 = t * BK;
            const float* aS = Ag + k0;
            const float* bS = Bg + k0;
            #pragma unroll
            for (int i = 0; i < 2; i++)      // A: 128 rows
                cp_async16(st + ldDst + i * 64 * ROWB,
                           aS + ldSrc + (size_t)i * 64 * K);
            #pragma unroll
            for (int i = 0; i < 4; i++)      // B: 256 rows
                cp_async16(st + A_STAGE + ldDst + i * 64 * ROWB,
                           bS + ldSrc + (size_t)i * 64 * K);
        }
        cp_commit();   // uniform one group per slot (possibly empty)
    };

    // fragment smem byte-offsets (relative to stage base)
    uint32_t aoff[4], boff[2];
    #pragma unroll
    for (int i = 0; i < 4; i++)
        aoff[i] = (uint32_t)((wm * 64 + i * 16 + (l & 15)) * ROWB
                             + (l >> 4) * 16);
    #pragma unroll
    for (int j = 0; j < 2; j++)
        boff[j] = (uint32_t)(A_STAGE
                             + (wn * 32 + j * 16 + (l & 7) + ((l >> 4) << 3)) * ROWB
                             + ((l >> 3) & 1) * 16);

    float acc[4][4][4];
    #pragma unroll
    for (int i = 0; i < 4; i++)
        #pragma unroll
        for (int j = 0; j < 4; j++)
            #pragma unroll
            for (int q = 0; q < 4; q++) acc[i][j][q] = 0.f;

    issue_tile(0);
    issue_tile(1);
    issue_tile(2);

    for (int it = 0; it < n_iters; ++it) {
        cp_wait_group<2>();          // tile `it` resident
        __syncthreads();             // all warps done with iter it-1
        issue_tile(it + 3);          // writes slot (it-1)%4: safe after barrier

        const uint32_t st = sb + (it & (STAGES - 1)) * STAGE_BYTES;
        #pragma unroll
        for (int ks = 0; ks < BK / 8; ks++) {
            uint32_t af[4][4], bf[2][4];
            #pragma unroll
            for (int i = 0; i < 4; i++)
                ldmatrix_x4(af[i], st + aoff[i] + ks * 32);
            #pragma unroll
            for (int j = 0; j < 2; j++)
                ldmatrix_x4(bf[j], st + boff[j] + ks * 32);
            #pragma unroll
            for (int i = 0; i < 4; i++) {
                mma_tf32(acc[i][0], af[i], &bf[0][0]);
                mma_tf32(acc[i][1], af[i], &bf[0][2]);
                mma_tf32(acc[i][2], af[i], &bf[1][0]);
                mma_tf32(acc[i][3], af[i], &bf[1][2]);
            }
        }
    }

    // ---- fused epilogue ----
    const int cRow = blockIdx.y * BM + wm * 64;
    const int cCol = blockIdx.x * BN + wn * 32;
    // decode partial: offset into the per-split partial buffer
    float* Cb = (MODE == 1)
        ? C + (size_t)blockIdx.z * 8192 * 2048
        : C;

    #pragma unroll
    for (int i = 0; i < 4; i++) {
        const int r0 = cRow + i * 16 + (l >> 2);
        #pragma unroll
        for (int j = 0; j < 4; j++) {
            const int col = cCol + j * 8 + (l & 3) * 2;
            float v0 = acc[i][j][0];
            float v1 = acc[i][j][1];
            float v2 = acc[i][j][2];
            float v3 = acc[i][j][3];
            if (MODE == 0) {
                const float2 bv = *reinterpret_cast<const float2*>(bias + col);
                const float2 tv = *reinterpret_cast<const float2*>(thr + col);
                v0 += bv.x; v1 += bv.y; v2 += bv.x; v3 += bv.y;
                v0 = (v0 > tv.x) ? round_tf32(v0) : 0.f;
                v1 = (v1 > tv.y) ? round_tf32(v1) : 0.f;
                v2 = (v2 > tv.x) ? round_tf32(v2) : 0.f;
                v3 = (v3 > tv.y) ? round_tf32(v3) : 0.f;
            }
            const size_t o0 = (size_t)r0 * Nout + col;
            const size_t o1 = (size_t)(r0 + 8) * Nout + col;
            *reinterpret_cast<float2*>(Cb + o0) = make_float2(v0, v1);
            *reinterpret_cast<float2*>(Cb + o1) = make_float2(v2, v3);
        }
    }
}

// ------------------------------- launcher ----------------------------------
extern "C" void kernel_launch(void* const* d_in, const int* in_sizes, int n_in,
                              void* d_out, int out_size) {
    const float* x     = (const float*)d_in[0];   // [8192, 2048]
    const float* W_enc = (const float*)d_in[1];   // [2048, 16384]
    const float* b_enc = (const float*)d_in[2];   // [16384]
    const float* thr   = (const float*)d_in[3];   // [16384]
    const float* W_dec = (const float*)d_in[4];   // [16384, 2048]
    const float* b_dec = (const float*)d_in[5];   // [2048]

    const int Nrows = 8192, D = 2048, S = 16384;

    float* recon = (float*)d_out;                       // [8192, 2048]
    float* feats = (float*)d_out + (size_t)Nrows * D;   // [8192, 16384]

    float *wEncT, *wDecT, *xR, *decPart, *biasPart, *biasEnc;
    cudaGetSymbolAddress((void**)&wEncT, g_WencT);
    cudaGetSymbolAddress((void**)&wDecT, g_WdecT);
    cudaGetSymbolAddress((void**)&xR, g_xR);
    cudaGetSymbolAddress((void**)&decPart, g_decPart);
    cudaGetSymbolAddress((void**)&biasPart, g_biasPart);
    cudaGetSymbolAddress((void**)&biasEnc, g_biasEnc);

    cudaFuncSetAttribute(sae_gemm<0>,
                         cudaFuncAttributeMaxDynamicSharedMemorySize, SMEM_TOTAL);
    cudaFuncSetAttribute(sae_gemm<1>,
                         cudaFuncAttributeMaxDynamicSharedMemorySize, SMEM_TOTAL);

    // fused prep: bias partials + both transposes + x rounding, one launch
    fused_prep<<<NB_ALL, 256>>>(W_enc, W_dec, x, b_dec,
                                wEncT, wDecT, xR, biasPart);
    bias_reduce_kernel<<<S / 256, 256>>>(biasPart, b_enc, biasEnc, S);

    // encode: feats = round_tf32(JumpReLU(xR @ W_enc + bias_eff)) -> d_out
    sae_gemm<0><<<dim3(S / BN, Nrows / BM), NT, SMEM_TOTAL>>>(
        xR, wEncT, biasEnc, thr, feats, D, S);

    // decode split-K: 1024 CTAs (6.92 waves vs 3.46) -> partials
    sae_gemm<1><<<dim3(D / BN, Nrows / BM, DEC_SPLIT), NT, SMEM_TOTAL>>>(
        feats, wDecT, nullptr, nullptr, decPart, S, D);

    // combine: recon = p0 + p1 + b_dec
    {
        size_t n4 = (size_t)Nrows * D / 4;
        dec_combine_kernel<<<(unsigned)((n4 + 255) / 256), 256>>>(
            decPart, b_dec, recon, D, n4);
    }
}

// round 16
// speedup vs baseline: 1.8137x; 1.1800x over previous
#include <cuda_runtime.h>
#include <cstdint>

// ===========================================================================
// JumpReLU SAE via mma.sync tf32 (round-15 best: 6075us) + mainloop residual:
//   (a) per-warp k-slice stagger -> spreads post-barrier LDSM burst
//   (b) issue_tile moved after compute -> barrier->first-LDSM path shortened
// Mainloop is smem-crossbar bound (246KB/iter @128B/cyc ~= 1968cyc floor);
// this round targets the ~230cyc/iter exposure above that floor.
// ===========================================================================

#define BM 128
#define BN 256
#define BK 32
#define STAGES 4
#define NT 512            // 16 warps: 2 (M) x 8 (N), warp tile 64x32

#define ROWB 144                      // (BK+4)*4 B; 9x16B rows -> conflict-free ldmatrix
#define A_STAGE (BM * ROWB)           // 18432 B
#define B_STAGE (BN * ROWB)           // 36864 B
#define STAGE_BYTES (A_STAGE + B_STAGE)          // 55296 B
#define SMEM_TOTAL (STAGES * STAGE_BYTES)        // 221184 B

#define BC_SPLIT 16       // split-K factor for bias correction
#define DEC_SPLIT 2       // decode split-K factor (wave quantization fix)

// fused-prep grid layout (block = 256 threads)
#define NB_BIAS (64 * BC_SPLIT)            // 1024
#define NB_TE   (512 * 64)                 // 32768  W_enc^T: C/32=512, R/32=64
#define NB_RD   16384                      // x round: 8192*2048/4/256
#define NB_TD   (64 * 512)                 // 32768  W_dec^T
#define NB_ALL  (NB_BIAS + NB_TE + NB_RD + NB_TD)

// ------------------------- device scratch (no allocs allowed) --------------
__device__ __align__(16) float g_WencT[(size_t)16384 * 2048];   // [n][k] tf32
__device__ __align__(16) float g_WdecT[(size_t)2048 * 16384];   // [n][k] tf32
__device__ __align__(16) float g_xR[(size_t)8192 * 2048];       // x tf32
__device__ __align__(16) float g_decPart[(size_t)DEC_SPLIT * 8192 * 2048];
__device__ __align__(16) float g_biasPart[BC_SPLIT * 16384];
__device__ __align__(16) float g_biasEnc[16384];

// ------------------------------ PTX helpers --------------------------------
__device__ __forceinline__ uint32_t smem_u32(const void* p) {
    uint32_t a;
    asm("{ .reg .u64 t; cvta.to.shared.u64 t, %1; cvt.u32.u64 %0, t; }"
        : "=r"(a) : "l"(p));
    return a;
}
__device__ __forceinline__ void cp_async16(uint32_t dst, const void* src) {
    asm volatile("cp.async.cg.shared.global [%0], [%1], 16;"
                 :: "r"(dst), "l"(src) : "memory");
}
__device__ __forceinline__ void cp_commit() {
    asm volatile("cp.async.commit_group;" ::: "memory");
}
template <int N>
__device__ __forceinline__ void cp_wait_group() {
    asm volatile("cp.async.wait_group %0;" :: "n"(N) : "memory");
}
__device__ __forceinline__ void ldmatrix_x4(uint32_t* r, uint32_t addr) {
    asm volatile("ldmatrix.sync.aligned.m8n8.x4.shared.b16 {%0, %1, %2, %3}, [%4];"
                 : "=r"(r[0]), "=r"(r[1]), "=r"(r[2]), "=r"(r[3]) : "r"(addr));
}
__device__ __forceinline__ float round_tf32(float v) {
    float d;
    asm("cvt.rna.tf32.f32 %0, %1;" : "=f"(d) : "f"(v));
    return d;
}
__device__ __forceinline__ void mma_tf32(float* c, const uint32_t* a,
                                         const uint32_t* b) {
    asm volatile(
        "mma.sync.aligned.m16n8k8.row.col.f32.tf32.tf32.f32 "
        "{%0, %1, %2, %3}, {%4, %5, %6, %7}, {%8, %9}, {%0, %1, %2, %3};"
        : "+f"(c[0]), "+f"(c[1]), "+f"(c[2]), "+f"(c[3])
        : "r"(a[0]), "r"(a[1]), "r"(a[2]), "r"(a[3]), "r"(b[0]), "r"(b[1]));
}

// ------------------------------- fused prep --------------------------------
__device__ __forceinline__ void transpose_body(const float* __restrict__ src,
                                               float* __restrict__ dst,
                                               int R, int C, int blk, int tid,
                                               float (*tile)[33]) {
    const int gx = C / 32;
    const int bx = blk % gx;
    const int by = blk / gx;
    const int tx = tid & 31;
    const int ty = tid >> 5;          // 0..7
    int x = bx * 32 + tx;
    int y = by * 32 + ty;
    #pragma unroll
    for (int j = 0; j < 32; j += 8)
        tile[ty + j][tx] = round_tf32(src[(size_t)(y + j) * C + x]);
    __syncthreads();
    x = by * 32 + tx;
    y = bx * 32 + ty;
    #pragma unroll
    for (int j = 0; j < 32; j += 8)
        dst[(size_t)(y + j) * R + x] = tile[tx][ty + j];
}

__global__ __launch_bounds__(256)
void fused_prep(const float* __restrict__ W_enc,   // [2048][16384]
                const float* __restrict__ W_dec,   // [16384][2048]
                const float* __restrict__ x,       // [8192][2048]
                const float* __restrict__ b_dec,   // [2048]
                float* __restrict__ wEncT,
                float* __restrict__ wDecT,
                float* __restrict__ xR,
                float* __restrict__ biasPart) {
    __shared__ float tile[32][33];
    const int tid = threadIdx.x;
    int b = blockIdx.x;

    if (b < NB_BIAS) {
        const int bx = b & 63;            // 64 n-blocks
        const int ky = b >> 6;            // 0..15
        const int n  = bx * 256 + tid;
        const int kc = 2048 / BC_SPLIT;   // 128
        const int k0 = ky * kc;
        float s = 0.f;
        #pragma unroll 4
        for (int k = k0; k < k0 + kc; k++)
            s += b_dec[k] * W_enc[(size_t)k * 16384 + n];
        biasPart[(size_t)ky * 16384 + n] = s;
        return;
    }
    b -= NB_BIAS;
    if (b < NB_TE) {   // W_encT = round(W_enc^T), R=2048, C=16384
        transpose_body(W_enc, wEncT, 2048, 16384, b, tid, tile);
        return;
    }
    b -= NB_TE;
    if (b < NB_RD) {   // xR = round(x)
        const size_t i = (size_t)b * 256 + tid;
        float4 v = reinterpret_cast<const float4*>(x)[i];
        v.x = round_tf32(v.x); v.y = round_tf32(v.y);
        v.z = round_tf32(v.z); v.w = round_tf32(v.w);
        reinterpret_cast<float4*>(xR)[i] = v;
        return;
    }
    b -= NB_RD;
    transpose_body(W_dec, wDecT, 16384, 2048, b, tid, tile);
}

// bias_eff[n] = b_enc[n] - sum_ky part[ky][n]   (deterministic reduce)
__global__ void bias_reduce_kernel(const float* __restrict__ part,
                                   const float* __restrict__ b_enc,
                                   float* __restrict__ out, int N) {
    const int n = blockIdx.x * blockDim.x + threadIdx.x;
    float s = 0.f;
    #pragma unroll
    for (int ky = 0; ky < BC_SPLIT; ky++)
        s += part[(size_t)ky * N + n];
    out[n] = b_enc[n] - s;
}

// recon[i] = p0[i] + p1[i] + b_dec[i % D]  (deterministic combine)
__global__ void dec_combine_kernel(const float* __restrict__ part,
                                   const float* __restrict__ b_dec,
                                   float* __restrict__ out,
                                   int D, size_t n4) {
    size_t i = (size_t)blockIdx.x * blockDim.x + threadIdx.x;
    if (i < n4) {
        const size_t half = n4;   // elements4 per partial
        float4 a = reinterpret_cast<const float4*>(part)[i];
        float4 b = reinterpret_cast<const float4*>(part)[i + half];
        const int col = (int)((i * 4) & (size_t)(D - 1));
        const float4 bd = *reinterpret_cast<const float4*>(b_dec + col);
        float4 o;
        o.x = a.x + b.x + bd.x;
        o.y = a.y + b.y + bd.y;
        o.z = a.z + b.z + bd.z;
        o.w = a.w + b.w + bd.w;
        reinterpret_cast<float4*>(out)[i] = o;
    }
}

// ------------------------------- main GEMM ---------------------------------
// MODE 0: encode  — JumpReLU epilogue, output tf32-rounded, full K
// MODE 1: decode partial — K split by blockIdx.z, raw accumulator out
template <int MODE>
__global__ __launch_bounds__(NT, 1)
void sae_gemm(const float* __restrict__ A,      // [M][K] K-contig, tf32 values
              const float* __restrict__ B,      // [Ntot][K] K-contig, tf32 values
              const float* __restrict__ bias,   // [Ntot] (MODE 0)
              const float* __restrict__ thr,    // [Ntot] (MODE 0)
              float* __restrict__ C,            // [M][Ntot] (or partials)
              int K, int Nout) {
    extern __shared__ __align__(16) char smem[];
    const uint32_t sb = smem_u32(smem);

    const int tid = threadIdx.x;
    const int wid = tid >> 5;
    const int l   = tid & 31;
    const int wm  = wid & 1;        // 0..1 (M)
    const int wn  = wid >> 1;       // 0..7 (N)
    const int ks0 = wid & 3;        // per-warp k-slice stagger

    const int Kc    = (MODE == 1) ? (K / DEC_SPLIT) : K;
    const int kbase = (MODE == 1) ? (blockIdx.z * Kc) : 0;

    const float* Ag = A + (size_t)blockIdx.y * BM * K + kbase;
    const float* Bg = B + (size_t)blockIdx.x * BN * K + kbase;

    const int n_iters = Kc / BK;

    // cp.async mapping: 16B chunks, 512 threads.
    const int ldRow = tid >> 3;          // 0..63
    const int ldChk = tid & 7;           // 0..7
    const size_t ldSrc  = (size_t)ldRow * K + ldChk * 4;
    const uint32_t ldDst = (uint32_t)(ldRow * ROWB + ldChk * 16);

    auto issue_tile = [&](int t) {
        if (t < n_iters) {
            const uint32_t st = sb + (t & (STAGES - 1)) * STAGE_BYTES;
            const int k0 = t * BK;
            const float* aS = Ag + k0;
            const float* bS = Bg + k0;
            #pragma unroll
            for (int i = 0; i < 2; i++)      // A: 128 rows
                cp_async16(st + ldDst + i * 64 * ROWB,
                           aS + ldSrc + (size_t)i * 64 * K);
            #pragma unroll
            for (int i = 0; i < 4; i++)      // B: 256 rows
                cp_async16(st + A_STAGE + ldDst + i * 64 * ROWB,
                           bS + ldSrc + (size_t)i * 64 * K);
        }
        cp_commit();   // uniform one group per slot (possibly empty)
    };

    // fragment smem byte-offsets (relative to stage base)
    uint32_t aoff[4], boff[2];
    #pragma unroll
    for (int i = 0; i < 4; i++)
        aoff[i] = (uint32_t)((wm * 64 + i * 16 + (l & 15)) * ROWB
                             + (l >> 4) * 16);
    #pragma unroll
    for (int j = 0; j < 2; j++)
        boff[j] = (uint32_t)(A_STAGE
                             + (wn * 32 + j * 16 + (l & 7) + ((l >> 4) << 3)) * ROWB
                             + ((l >> 3) & 1) * 16);

    float acc[4][4][4];
    #pragma unroll
    for (int i = 0; i < 4; i++)
        #pragma unroll
        for (int j = 0; j < 4; j++)
            #pragma unroll
            for (int q = 0; q < 4; q++) acc[i][j][q] = 0.f;

    auto compute_tile = [&](int t) {
        const uint32_t st = sb + (t & (STAGES - 1)) * STAGE_BYTES;
        #pragma unroll
        for (int s = 0; s < BK / 8; s++) {
            const int ks = (ks0 + s) & 3;    // staggered k-slice order
            uint32_t af[4][4], bf[2][4];
            #pragma unroll
            for (int i = 0; i < 4; i++)
                ldmatrix_x4(af[i], st + aoff[i] + ks * 32);
            #pragma unroll
            for (int j = 0; j < 2; j++)
                ldmatrix_x4(bf[j], st + boff[j] + ks * 32);
            #pragma unroll
            for (int i = 0; i < 4; i++) {
                mma_tf32(acc[i][0], af[i], &bf[0][0]);
                mma_tf32(acc[i][1], af[i], &bf[0][2]);
                mma_tf32(acc[i][2], af[i], &bf[1][0]);
                mma_tf32(acc[i][3], af[i], &bf[1][2]);
            }
        }
    };

    issue_tile(0);
    issue_tile(1);
    issue_tile(2);

    // Schedule: wait -> sync -> compute -> issue.
    // wait<2> at iter it: outstanding groups <= {it+1, it+2} -> tile it ready.
    // issue(it+3) writes slot (it-1)&3, free since all warps passed the sync
    // (which follows their compute of tile it-1 in program order).
    for (int it = 0; it < n_iters; ++it) {
        cp_wait_group<2>();
        __syncthreads();
        compute_tile(it);
        issue_tile(it + 3);
    }

    // ---- fused epilogue ----
    const int cRow = blockIdx.y * BM + wm * 64;
    const int cCol = blockIdx.x * BN + wn * 32;
    float* Cb = (MODE == 1)
        ? C + (size_t)blockIdx.z * 8192 * 2048
        : C;

    #pragma unroll
    for (int i = 0; i < 4; i++) {
        const int r0 = cRow + i * 16 + (l >> 2);
        #pragma unroll
        for (int j = 0; j < 4; j++) {
            const int col = cCol + j * 8 + (l & 3) * 2;
            float v0 = acc[i][j][0];
            float v1 = acc[i][j][1];
            float v2 = acc[i][j][2];
            float v3 = acc[i][j][3];
            if (MODE == 0) {
                const float2 bv = *reinterpret_cast<const float2*>(bias + col);
                const float2 tv = *reinterpret_cast<const float2*>(thr + col);
                v0 += bv.x; v1 += bv.y; v2 += bv.x; v3 += bv.y;
                v0 = (v0 > tv.x) ? round_tf32(v0) : 0.f;
                v1 = (v1 > tv.y) ? round_tf32(v1) : 0.f;
                v2 = (v2 > tv.x) ? round_tf32(v2) : 0.f;
                v3 = (v3 > tv.y) ? round_tf32(v3) : 0.f;
            }
            const size_t o0 = (size_t)r0 * Nout + col;
            const size_t o1 = (size_t)(r0 + 8) * Nout + col;
            *reinterpret_cast<float2*>(Cb + o0) = make_float2(v0, v1);
            *reinterpret_cast<float2*>(Cb + o1) = make_float2(v2, v3);
        }
    }
}

// ------------------------------- launcher ----------------------------------
extern "C" void kernel_launch(void* const* d_in, const int* in_sizes, int n_in,
                              void* d_out, int out_size) {
    const float* x     = (const float*)d_in[0];   // [8192, 2048]
    const float* W_enc = (const float*)d_in[1];   // [2048, 16384]
    const float* b_enc = (const float*)d_in[2];   // [16384]
    const float* thr   = (const float*)d_in[3];   // [16384]
    const float* W_dec = (const float*)d_in[4];   // [16384, 2048]
    const float* b_dec = (const float*)d_in[5];   // [2048]

    const int Nrows = 8192, D = 2048, S = 16384;

    float* recon = (float*)d_out;                       // [8192, 2048]
    float* feats = (float*)d_out + (size_t)Nrows * D;   // [8192, 16384]

    float *wEncT, *wDecT, *xR, *decPart, *biasPart, *biasEnc;
    cudaGetSymbolAddress((void**)&wEncT, g_WencT);
    cudaGetSymbolAddress((void**)&wDecT, g_WdecT);
    cudaGetSymbolAddress((void**)&xR, g_xR);
    cudaGetSymbolAddress((void**)&decPart, g_decPart);
    cudaGetSymbolAddress((void**)&biasPart, g_biasPart);
    cudaGetSymbolAddress((void**)&biasEnc, g_biasEnc);

    cudaFuncSetAttribute(sae_gemm<0>,
                         cudaFuncAttributeMaxDynamicSharedMemorySize, SMEM_TOTAL);
    cudaFuncSetAttribute(sae_gemm<1>,
                         cudaFuncAttributeMaxDynamicSharedMemorySize, SMEM_TOTAL);

    // fused prep: bias partials + both transposes + x rounding, one launch
    fused_prep<<<NB_ALL, 256>>>(W_enc, W_dec, x, b_dec,
                                wEncT, wDecT, xR, biasPart);
    bias_reduce_kernel<<<S / 256, 256>>>(biasPart, b_enc, biasEnc, S);

    // encode: feats = round_tf32(JumpReLU(xR @ W_enc + bias_eff)) -> d_out
    sae_gemm<0><<<dim3(S / BN, Nrows / BM), NT, SMEM_TOTAL>>>(
        xR, wEncT, biasEnc, thr, feats, D, S);

    // decode split-K: 1024 CTAs (6.92 waves vs 3.46) -> partials
    sae_gemm<1><<<dim3(D / BN, Nrows / BM, DEC_SPLIT), NT, SMEM_TOTAL>>>(
        feats, wDecT, nullptr, nullptr, decPart, S, D);

    // combine: recon = p0 + p1 + b_dec
    {
        size_t n4 = (size_t)Nrows * D / 4;
        dec_combine_kernel<<<(unsigned)((n4 + 255) / 256), 256>>>(
            decPart, b_dec, recon, D, n4);
    }
}